// round 8
// baseline (speedup 1.0000x reference)
#include <cuda_runtime.h>
#include <cstdint>

#define N_NODES 100000
#define N_EDGES 1600000
#define IN_DIM  256
#define HID_DIM 64
#define OUT_DIM 64

// -------- scratch (device globals: allocation-free per harness rules) --------
__device__ __align__(16) float g_ew[N_EDGES];        // normalized edge weights
__device__ __align__(16) float g_deg[N_NODES];       // degree (init 1.0 self-loop)
__device__ __align__(16) float g_dinv[N_NODES];      // deg^{-1/2}
__device__ __align__(16) float g_y1[N_NODES * HID_DIM];   // x @ W1
__device__ __align__(16) float g_agg1[N_NODES * HID_DIM]; // layer-1 aggregation
__device__ __align__(16) float g_y2[N_NODES * OUT_DIM];   // h @ W2
// CSR (sorted by destination col)
__device__ int   g_count[N_NODES];      // in-degree histogram
__device__ int   g_rowptr[N_NODES + 1]; // exclusive prefix
__device__ int   g_pos[N_NODES];        // fill cursors
__device__ __align__(16) int   g_srow[N_EDGES];   // source row, sorted by col
__device__ __align__(16) float g_snorm[N_EDGES];  // norm, sorted by col
__device__ int g_min, g_max;
__device__ int g_ei64, g_ec64;   // 1 if buffer really is int64, 0 if int32

// flag-selected integer load (handles JAX silently demoting int64 -> int32)
__device__ __forceinline__ long long ld_int(const void* p, long long i, int is64) {
    if (is64) return ((const long long*)p)[i];
    return (long long)((const int*)p)[i];
}

// ------------------------------- prep kernels -------------------------------
__global__ void k_init() {
    int i = blockIdx.x * blockDim.x + threadIdx.x;
    if (i < N_NODES) { g_deg[i] = 1.0f; g_count[i] = 0; }
    if (i == 0) {
        g_min = 0x7fffffff; g_max = (int)0x80000000;
        g_ei64 = 1; g_ec64 = 1;
    }
}

__global__ void k_detect(const void* ei, const void* ec) {
    int bad_ei = 0, bad_ec = 0;
    for (int i = threadIdx.x; i < 4096; i += blockDim.x) {
        long long v = ((const long long*)ei)[i];
        if (v < 0 || v >= N_NODES) bad_ei = 1;
        long long w = ((const long long*)ec)[i];
        if (w < 0 || w >= (1LL << 20)) bad_ec = 1;
    }
    if (bad_ei) atomicAnd(&g_ei64, 0);
    if (bad_ec) atomicAnd(&g_ec64, 0);
}

__global__ void k_minmax(const void* __restrict__ ec) {
    int is64 = g_ec64;
    int lmin = 0x7fffffff, lmax = (int)0x80000000;
    for (int e = blockIdx.x * blockDim.x + threadIdx.x; e < N_EDGES;
         e += gridDim.x * blockDim.x) {
        int v = (int)ld_int(ec, e, is64);
        lmin = min(lmin, v);
        lmax = max(lmax, v);
    }
    #pragma unroll
    for (int o = 16; o; o >>= 1) {
        lmin = min(lmin, __shfl_xor_sync(0xffffffffu, lmin, o));
        lmax = max(lmax, __shfl_xor_sync(0xffffffffu, lmax, o));
    }
    if ((threadIdx.x & 31) == 0) {
        atomicMin(&g_min, lmin);
        atomicMax(&g_max, lmax);
    }
}

// ew + weighted degree + in-degree histogram (fused)
__global__ void k_ew_deg(const void* __restrict__ ec,
                         const void* __restrict__ ei) {
    int e = blockIdx.x * blockDim.x + threadIdx.x;
    if (e >= N_EDGES) return;
    float mn = (float)g_min;
    float inv = 1.0f / ((float)g_max - mn);
    float w = ((float)(int)ld_int(ec, e, g_ec64) - mn) * inv;
    g_ew[e] = w;
    int c = (int)ld_int(ei, (long long)N_EDGES + e, g_ei64);
    if ((unsigned)c < (unsigned)N_NODES) {
        atomicAdd(&g_deg[c], w);
        atomicAdd(&g_count[c], 1);
    }
}

__global__ void k_dinv() {
    int i = blockIdx.x * blockDim.x + threadIdx.x;
    if (i >= N_NODES) return;
    float d = g_deg[i];
    g_dinv[i] = d > 0.0f ? rsqrtf(d) : 0.0f;
}

// single-block exclusive scan over g_count -> g_rowptr / g_pos
__global__ void k_scan() {
    constexpr int T = 1024;
    constexpr int CHUNK = (N_NODES + T - 1) / T;  // 98
    __shared__ int tmp[T];
    int tid = threadIdx.x;
    int base = tid * CHUNK;
    int s = 0;
    #pragma unroll 4
    for (int i = 0; i < CHUNK; i++) {
        int idx = base + i;
        if (idx < N_NODES) s += g_count[idx];
    }
    tmp[tid] = s;
    __syncthreads();
    #pragma unroll
    for (int off = 1; off < T; off <<= 1) {
        int v = (tid >= off) ? tmp[tid - off] : 0;
        __syncthreads();
        tmp[tid] += v;
        __syncthreads();
    }
    int run = tmp[tid] - s;   // exclusive prefix for this chunk
    for (int i = 0; i < CHUNK; i++) {
        int idx = base + i;
        if (idx < N_NODES) {
            g_rowptr[idx] = run;
            g_pos[idx] = run;
            run += g_count[idx];
        }
    }
    if (base < N_NODES && base + CHUNK >= N_NODES)
        g_rowptr[N_NODES] = run;
}

// fill CSR: (srow, norm) sorted by destination
__global__ void k_fill(const void* __restrict__ ei) {
    int e = blockIdx.x * blockDim.x + threadIdx.x;
    if (e >= N_EDGES) return;
    int is64 = g_ei64;
    int r = (int)ld_int(ei, e, is64);
    int c = (int)ld_int(ei, (long long)N_EDGES + e, is64);
    if ((unsigned)r >= (unsigned)N_NODES || (unsigned)c >= (unsigned)N_NODES)
        return;
    float nrm = g_dinv[r] * g_ew[e] * g_dinv[c];
    int p = atomicAdd(&g_pos[c], 1);
    g_srow[p] = r;
    g_snorm[p] = nrm;
}

// --------------------------------- GEMM -------------------------------------
// y = act(xin) @ W
// LAYER 1: xin = x (external), K=256 -> g_y1
// LAYER 2: xin = relu(g_agg1 + b1), K=64 -> g_y2
template <int LAYER>
__global__ void k_gemm(const float* __restrict__ x_ext,
                       const float* __restrict__ W,
                       const float* __restrict__ bias) {
    constexpr int K  = (LAYER == 1) ? IN_DIM : HID_DIM;
    constexpr int KC = (LAYER == 1) ? 128 : 64;   // chunk rows of W
    __shared__ __align__(16) float2 sW[KC * 32];  // [KC][32] float2 (row-major W)

    int warp = threadIdx.x >> 5, lane = threadIdx.x & 31;
    int row0 = (blockIdx.x * 8 + warp) * 4;

    float xr[4][K / 32];
    #pragma unroll
    for (int r = 0; r < 4; r++) {
        #pragma unroll
        for (int j = 0; j < K / 32; j++) {
            float v;
            if (LAYER == 1) {
                v = x_ext[(row0 + r) * K + j * 32 + lane];
            } else {
                v = g_agg1[(row0 + r) * K + j * 32 + lane] + bias[j * 32 + lane];
                v = fmaxf(v, 0.0f);
            }
            xr[r][j] = v;
        }
    }

    float2 acc[4];
    #pragma unroll
    for (int r = 0; r < 4; r++) { acc[r].x = 0.0f; acc[r].y = 0.0f; }

    #pragma unroll
    for (int ch = 0; ch < K / KC; ch++) {
        {
            const float4* Wv = (const float4*)(W + ch * KC * 64);
            float4* sWv = (float4*)sW;
            for (int i = threadIdx.x; i < KC * 16; i += 256) sWv[i] = Wv[i];
        }
        __syncthreads();

        #pragma unroll
        for (int j = 0; j < KC / 32; j++) {
            int jj = ch * (KC / 32) + j;
            #pragma unroll 8
            for (int kk = 0; kk < 32; kk++) {
                float2 w = sW[(j * 32 + kk) * 32 + lane];
                #pragma unroll
                for (int r = 0; r < 4; r++) {
                    float xv = __shfl_sync(0xffffffffu, xr[r][jj], kk);
                    acc[r].x += xv * w.x;
                    acc[r].y += xv * w.y;
                }
            }
        }
        __syncthreads();
    }

    #pragma unroll
    for (int r = 0; r < 4; r++) {
        int row = row0 + r;
        if constexpr (LAYER == 1)
            ((float2*)g_y1)[row * 32 + lane] = acc[r];
        else
            ((float2*)g_y2)[row * 32 + lane] = acc[r];
    }
}

// ----------------------------- CSR gather -----------------------------------
// warp per node: acc = y[i]*dinv^2 (self loop) + sum over in-edges y[src]*norm
// LAYER 2 fuses bias2 + output writes + log_softmax (no k_final pass).
template <int LAYER>
__global__ void k_gather(const float* __restrict__ b2,
                         float* __restrict__ out, int write_lsm) {
    int t = blockIdx.x * blockDim.x + threadIdx.x;
    int i = t >> 5;
    int lane = t & 31;
    if (i >= N_NODES) return;

    const float2* yv = (LAYER == 1) ? (const float2*)g_y1 : (const float2*)g_y2;

    float di = g_dinv[i];
    float sl = di * di;
    float2 self = yv[i * 32 + lane];
    float2 acc;
    acc.x = self.x * sl;
    acc.y = self.y * sl;

    int p = g_rowptr[i];
    int p1 = g_rowptr[i + 1];
    for (; p + 2 <= p1; p += 2) {
        int   r0 = g_srow[p],    r1 = g_srow[p + 1];
        float w0 = g_snorm[p],   w1 = g_snorm[p + 1];
        float2 v0 = yv[r0 * 32 + lane];
        float2 v1 = yv[r1 * 32 + lane];
        acc.x += v0.x * w0 + v1.x * w1;
        acc.y += v0.y * w0 + v1.y * w1;
    }
    if (p < p1) {
        int   r0 = g_srow[p];
        float w0 = g_snorm[p];
        float2 v0 = yv[r0 * 32 + lane];
        acc.x += v0.x * w0;
        acc.y += v0.y * w0;
    }

    if constexpr (LAYER == 1) {
        ((float2*)g_agg1)[i * 32 + lane] = acc;
    } else {
        acc.x += b2[2 * lane];
        acc.y += b2[2 * lane + 1];
        ((float2*)out)[i * 32 + lane] = acc;  // node_embeddings
        if (!write_lsm) return;
        float m = fmaxf(acc.x, acc.y);
        #pragma unroll
        for (int o = 16; o; o >>= 1)
            m = fmaxf(m, __shfl_xor_sync(0xffffffffu, m, o));
        float s = expf(acc.x - m) + expf(acc.y - m);
        #pragma unroll
        for (int o = 16; o; o >>= 1)
            s += __shfl_xor_sync(0xffffffffu, s, o);
        float lse = m + logf(s);
        float2 o2; o2.x = acc.x - lse; o2.y = acc.y - lse;
        ((float2*)(out + (size_t)N_NODES * OUT_DIM))[i * 32 + lane] = o2;
    }
}

// --------------------------------- launch ------------------------------------
extern "C" void kernel_launch(void* const* d_in, const int* in_sizes, int n_in,
                              void* d_out, int out_size) {
    const float* x = nullptr;
    const void *ei = nullptr, *ec = nullptr;
    const float *W1 = nullptr, *b1 = nullptr, *W2 = nullptr, *b2 = nullptr;
    for (int i = 0; i < n_in; i++) {
        int s = in_sizes[i];
        if (s == N_NODES * IN_DIM)       x  = (const float*)d_in[i];
        else if (s == 2 * N_EDGES)       ei = d_in[i];
        else if (s == N_EDGES)           ec = d_in[i];
        else if (s == IN_DIM * HID_DIM)  W1 = (const float*)d_in[i];
        else if (s == HID_DIM * OUT_DIM) W2 = (const float*)d_in[i];
        else if (s == HID_DIM) {
            if (!b1) b1 = (const float*)d_in[i];
            else     b2 = (const float*)d_in[i];
        }
    }
    float* out = (float*)d_out;
    if (!x || !ei || !ec || !W1 || !b1 || !W2 || !b2) return;

    int write_lsm = (out_size >= 2 * N_NODES * OUT_DIM) ? 1 : 0;

    k_init<<<(N_NODES + 255) / 256, 256>>>();
    k_detect<<<1, 256>>>(ei, ec);
    k_minmax<<<512, 256>>>(ec);
    k_ew_deg<<<(N_EDGES + 255) / 256, 256>>>(ec, ei);
    k_dinv<<<(N_NODES + 255) / 256, 256>>>();
    k_scan<<<1, 1024>>>();
    k_fill<<<(N_EDGES + 255) / 256, 256>>>(ei);

    // layer 1: y1 = x@W1, agg1 = Â·y1 via CSR gather
    k_gemm<1><<<N_NODES / 32, 256>>>(x, W1, b1);
    k_gather<1><<<(N_NODES * 32 + 255) / 256, 256>>>(b2, out, write_lsm);

    // layer 2: y2 = relu(agg1+b1)@W2, then gather + bias2 + log_softmax fused
    k_gemm<2><<<N_NODES / 32, 256>>>(x, W2, b1);
    k_gather<2><<<(N_NODES * 32 + 255) / 256, 256>>>(b2, out, write_lsm);
}